// round 9
// baseline (speedup 1.0000x reference)
#include <cuda_runtime.h>
#include <cstdint>

#define B_ 64
#define S_ 512
#define H_ 1024
#define V_ 128
#define THREADS_A 256
#define HB (H_ * B_)   /* 65536 floats per time slot, layout [h][b] */
#define WPAD 1036      /* w_sm column stride (floats), 16B-aligned */

// Hidden-state history, layout (slot, h, b); slot 0 = initial h (transposed),
// slot t+1 = hidden after step t.
__device__ __align__(16) float g_hid[(size_t)(S_ + 1) * HB];
// One full-barrier counter per batch-group (4 pools of 32 CTAs), 128B apart.
__device__ unsigned int g_cntb[4 * 32];

// ---------------------------------------------------------------------------
__global__ void rnn_init(const float* __restrict__ h0) {
    int i = blockIdx.x * blockDim.x + threadIdx.x;
    if (i < 4 * 32) g_cntb[i] = 0u;
    if (i < HB) {
        int b = i >> 10;        // i = b*1024 + h
        int hh = i & 1023;
        g_hid[(size_t)hh * B_ + b] = h0[i];
    }
}

// 8-k prefetch (L2-only loads; every address is read exactly once, ever)
#define PREF(buf, base)                                                        \
    _Pragma("unroll")                                                          \
    for (int u = 0; u < 8; ++u)                                                \
        buf[u] = __ldcg((const float4*)((base) + (size_t)u * B_));

// 8-k FMA block: acc[0..3] = col c0 x 4 batches, acc[4..7] = col c0+1
#define COMP(buf, wja, wjb)                                                    \
    _Pragma("unroll")                                                          \
    for (int u = 0; u < 8; u += 4) {                                           \
        float4 wa4 = *(const float4*)((wja) + u);                              \
        float4 wb4 = *(const float4*)((wjb) + u);                              \
        _Pragma("unroll")                                                      \
        for (int v = 0; v < 4; ++v) {                                          \
            float4 hv = buf[u + v];                                            \
            float wax = (&wa4.x)[v];                                           \
            float wbx = (&wb4.x)[v];                                           \
            acc[0] += hv.x * wax; acc[1] += hv.y * wax;                        \
            acc[2] += hv.z * wax; acc[3] += hv.w * wax;                        \
            acc[4] += hv.x * wbx; acc[5] += hv.y * wbx;                        \
            acc[6] += hv.z * wbx; acc[7] += hv.w * wbx;                        \
        }                                                                      \
    }

// ---------------------------------------------------------------------------
// Persistent recurrence. 128 CTAs x 256 threads. CTA (bg, cg) owns
// batches [16bg,16bg+16) x cols [32cg,32cg+32). Four decoupled pools of 32
// CTAs (per bg) with the R1-proven full-barrier idiom. h streamed straight
// from L2 into registers (double-buffered, 8-k prefetch) — no smem staging,
// so warps progress independently between barrier and reduction.
// ---------------------------------------------------------------------------
__global__ __launch_bounds__(THREADS_A, 1) void rnn_recur(
    const int* __restrict__ x, const float* __restrict__ W_xh,
    const float* __restrict__ W_hh, const float* __restrict__ b_h,
    float* __restrict__ hfinal_out)
{
    extern __shared__ float sm[];
    float* w_sm   = sm;                              // 32 * WPAD            ~130KB
    float* wxh_sm = w_sm + 32 * WPAD;                // 128 * 32              16KB
    float* red_sm = wxh_sm + V_ * 32;                // 256 * 8                8KB
    float* bh_sm  = red_sm + THREADS_A * 8;          // 32
    int*   x_sm   = (int*)(bh_sm + 32);              // 16

    const int tid   = threadIdx.x;
    const int bg    = blockIdx.x >> 5;               // batch group 0..3
    const int cg    = blockIdx.x & 31;               // col group   0..31
    const int cbase = cg * 32;
    const int boff  = bg * 16;

    for (int i = tid; i < H_ * 32; i += THREADS_A) {
        int k = i >> 5, c = i & 31;
        w_sm[c * WPAD + k] = W_hh[(size_t)k * H_ + cbase + c];
    }
    for (int i = tid; i < V_ * 32; i += THREADS_A) {
        int v = i >> 5, c = i & 31;
        wxh_sm[i] = W_xh[(size_t)v * H_ + cbase + c];
    }
    if (tid < 32) bh_sm[tid] = b_h[cbase + tid];
    __syncthreads();

    const int g  = tid & 63;        // 64 groups = 4 batch-quads x 16 col-pairs
    const int kg = tid >> 6;        // k-split group 0..3 (256 k each)
    const int b0 = (g & 3) * 4;     // 4 consecutive local batches
    const int c0 = (g >> 2) * 2;    // 2 consecutive local cols

    // Parallel-tail mapping (R7/R8-proven): 2 outputs per thread.
    const int tcol = tid >> 3;            // 0..31
    const int tb   = (tid & 7) * 2;       // 0,2,..,14
    const int tg   = (tcol >> 1) * 4 + (tb >> 2);
    const int ti   = (tcol & 1) * 4 + (tb & 3);

    const float* wa_base = w_sm + c0 * WPAD + kg * 256;
    const float* wb_base = wa_base + WPAD;

    for (int t = 0; t < S_; ++t) {
        const float* hp = g_hid + (size_t)t * HB + (size_t)(kg * 256) * B_ + boff + b0;
        if (tid < 16) x_sm[tid] = x[(size_t)(boff + tid) * S_ + t];

        float acc[8];
#pragma unroll
        for (int i = 0; i < 8; ++i) acc[i] = 0.f;

        float4 hbA[8], hbB[8];
        PREF(hbA, hp);                                   // k [0,8)
#pragma unroll 1
        for (int jo = 0; jo < 240; jo += 16) {
            PREF(hbB, hp + (size_t)(jo + 8) * B_);       // k [jo+8, jo+16)
            COMP(hbA, wa_base + jo, wb_base + jo);       // k [jo, jo+8)
            PREF(hbA, hp + (size_t)(jo + 16) * B_);      // k [jo+16, jo+24)
            COMP(hbB, wa_base + jo + 8, wb_base + jo + 8);
        }
        // Epilogue: hbA holds k [240,248)
        PREF(hbB, hp + (size_t)248 * B_);                // k [248,256)
        COMP(hbA, wa_base + 240, wb_base + 240);
        COMP(hbB, wa_base + 248, wb_base + 248);

        // k-split partials -> smem
        *(float4*)(red_sm + tid * 8)     = make_float4(acc[0], acc[1], acc[2], acc[3]);
        *(float4*)(red_sm + tid * 8 + 4) = make_float4(acc[4], acc[5], acc[6], acc[7]);
        __syncthreads();

        // Parallel tail: reduce 4 partials for 2 outputs, tanh, store h[t+1].
        {
            float s0 = 0.f, s1 = 0.f;
#pragma unroll
            for (int kk = 0; kk < 4; ++kk) {
                float2 v = *(const float2*)&red_sm[(kk * 64 + tg) * 8 + ti];
                s0 += v.x; s1 += v.y;
            }
            float wb0 = wxh_sm[x_sm[tb] * 32 + tcol];
            float wb1 = wxh_sm[x_sm[tb + 1] * 32 + tcol];
            float v0 = tanhf(s0 + wb0 + bh_sm[tcol]);
            float v1 = tanhf(s1 + wb1 + bh_sm[tcol]);
            *(float2*)&g_hid[(size_t)(t + 1) * HB +
                             (size_t)(cbase + tcol) * B_ + boff + tb] =
                make_float2(v0, v1);
            if (t == S_ - 1) {
                hfinal_out[(size_t)(boff + tb) * H_ + cbase + tcol]     = v0;
                hfinal_out[(size_t)(boff + tb + 1) * H_ + cbase + tcol] = v1;
            }
        }

        // R1-proven full barrier, among this batch-group's 32 CTAs only.
        __threadfence();
        __syncthreads();
        if (tid == 0) {
            unsigned target = (unsigned)(t + 1) * 32u;
            atomicAdd(&g_cntb[bg * 32], 1u);
            volatile unsigned* vc = &g_cntb[bg * 32];
            while ((int)(*vc - target) < 0) { }
            __threadfence();
        }
        __syncthreads();
    }
}

// ---------------------------------------------------------------------------
// logits = hidden @ W_out + b_out.  M=32768 (m = t*64+b), N=128, K=1024.
// A read from g_hid (t+1, k, b). 256 CTAs, 128x128 tile, 8x8 micro. (proven)
// ---------------------------------------------------------------------------
__global__ __launch_bounds__(256) void rnn_logits(
    const float* __restrict__ W_out, const float* __restrict__ b_out,
    float* __restrict__ out)
{
    __shared__ float a_sm[32][128];
    __shared__ float b_sm[32][128];
    const int tid = threadIdx.x;
    const int M0  = blockIdx.x * 128;
    const int t0  = M0 >> 6;
    const int tx  = tid & 15, ty = tid >> 4;

    float acc[8][8];
#pragma unroll
    for (int i = 0; i < 8; ++i)
#pragma unroll
        for (int j = 0; j < 8; ++j) acc[i][j] = 0.f;

    for (int kt = 0; kt < 32; ++kt) {
        int k0 = kt * 32;
#pragma unroll
        for (int j2 = 0; j2 < 4; ++j2) {
            int q = tid + j2 * 256;
            int k = q >> 5;
            int m = (q & 31) << 2;
            const float* asrc = g_hid + (size_t)(t0 + (m >> 6) + 1) * HB +
                                (size_t)(k0 + k) * B_ + (m & 63);
            *(float4*)&a_sm[k][m] = *(const float4*)asrc;
            *(float4*)&b_sm[k][m] = *(const float4*)&W_out[(size_t)(k0 + k) * V_ + m];
        }
        __syncthreads();
#pragma unroll
        for (int k = 0; k < 32; ++k) {
            float4 a0 = *(float4*)&a_sm[k][ty * 8];
            float4 a1 = *(float4*)&a_sm[k][ty * 8 + 4];
            float4 w0 = *(float4*)&b_sm[k][tx * 8];
            float4 w1 = *(float4*)&b_sm[k][tx * 8 + 4];
            float av[8] = {a0.x, a0.y, a0.z, a0.w, a1.x, a1.y, a1.z, a1.w};
            float bv[8] = {w0.x, w0.y, w0.z, w0.w, w1.x, w1.y, w1.z, w1.w};
#pragma unroll
            for (int i = 0; i < 8; ++i)
#pragma unroll
                for (int j = 0; j < 8; ++j) acc[i][j] += av[i] * bv[j];
        }
        __syncthreads();
    }

    float bo[8];
#pragma unroll
    for (int j = 0; j < 8; ++j) bo[j] = b_out[tx * 8 + j];
#pragma unroll
    for (int i = 0; i < 8; ++i) {
        int mg = M0 + ty * 8 + i;
        int tt = mg >> 6, b = mg & 63;
        float* op = out + ((size_t)b * S_ + tt) * V_ + tx * 8;
        *(float4*)op       = make_float4(acc[i][0] + bo[0], acc[i][1] + bo[1],
                                         acc[i][2] + bo[2], acc[i][3] + bo[3]);
        *(float4*)(op + 4) = make_float4(acc[i][4] + bo[4], acc[i][5] + bo[5],
                                         acc[i][6] + bo[6], acc[i][7] + bo[7]);
    }
}

// ---------------------------------------------------------------------------
extern "C" void kernel_launch(void* const* d_in, const int* in_sizes, int n_in,
                              void* d_out, int out_size) {
    (void)in_sizes; (void)n_in; (void)out_size;
    const int*   x     = (const int*)  d_in[0];
    const float* h0    = (const float*)d_in[1];
    const float* W_xh  = (const float*)d_in[2];
    const float* W_hh  = (const float*)d_in[3];
    const float* b_h   = (const float*)d_in[4];
    const float* W_out = (const float*)d_in[5];
    const float* b_out = (const float*)d_in[6];
    float* out = (float*)d_out;

    const int SMEM_A = (32 * WPAD + V_ * 32 + THREADS_A * 8 + 32)
                           * (int)sizeof(float) + 16 * (int)sizeof(int);
    cudaFuncSetAttribute(rnn_recur, cudaFuncAttributeMaxDynamicSharedMemorySize, SMEM_A);

    rnn_init<<<(HB + 255) / 256, 256>>>(h0);
    rnn_recur<<<128, THREADS_A, SMEM_A>>>(x, W_xh, W_hh, b_h,
                                          out + (size_t)B_ * S_ * V_);
    rnn_logits<<<(B_ * S_) / 128, 256>>>(W_out, b_out, out);
}

// round 10
// speedup vs baseline: 1.2722x; 1.2722x over previous
#include <cuda_runtime.h>
#include <cstdint>

#define B_ 64
#define S_ 512
#define H_ 1024
#define V_ 128
#define THREADS_A 512
#define HB (H_ * B_)   /* 65536 floats per time slot, layout [h][b] */
#define WPAD 1036      /* w_sm column stride (floats), 16B-aligned */

// Hidden-state history, layout (slot, h, b); slot 0 = initial h (transposed),
// slot t+1 = hidden after step t.
__device__ __align__(16) float g_hid[(size_t)(S_ + 1) * HB];
// One full-barrier counter per batch-group (4 pools of 32 CTAs), 128B apart.
__device__ unsigned int g_cntb[4 * 32];

// ---------------------------------------------------------------------------
__global__ void rnn_init(const float* __restrict__ h0) {
    int i = blockIdx.x * blockDim.x + threadIdx.x;
    if (i < 4 * 32) g_cntb[i] = 0u;
    if (i < HB) {
        int b = i >> 10;        // i = b*1024 + h
        int hh = i & 1023;
        g_hid[(size_t)hh * B_ + b] = h0[i];
    }
}

// ---------------------------------------------------------------------------
// cp.async staging of one k-tile of h: 512 k-rows x 16 batches = 32 KB.
// ---------------------------------------------------------------------------
__device__ __forceinline__ void stage_tile(uint32_t dst_s, const float* src_base, int tid) {
#pragma unroll
    for (int j = 0; j < 4; ++j) {
        int c = tid + j * THREADS_A;               // 0..2047 16B chunks
        int row = c >> 2, q = c & 3;
        asm volatile("cp.async.cg.shared.global [%0], [%1], 16;\n"
                     :: "r"(dst_s + (uint32_t)c * 16u),
                        "l"(src_base + (size_t)row * B_ + q * 4)
                     : "memory");
    }
}

// ---------------------------------------------------------------------------
// Persistent recurrence. 128 CTAs x 512 threads (16 warps — 4/SMSP for LDS
// latency hiding). CTA (bg, cg) owns batches [16bg,16bg+16) x cols
// [32cg,32cg+32). Four decoupled pools of 32 CTAs (per bg), R1-proven
// full-barrier idiom. Same staging/inner-product structure as the 4139us R8.
// ---------------------------------------------------------------------------
__global__ __launch_bounds__(THREADS_A, 1) void rnn_recur(
    const int* __restrict__ x, const float* __restrict__ W_xh,
    const float* __restrict__ W_hh, const float* __restrict__ b_h,
    float* __restrict__ hfinal_out)
{
    extern __shared__ float sm[];
    float* h_sm   = sm;                              // 2 * 512 * 16 (double buffer) 64KB
    float* w_sm   = h_sm + 2 * 512 * 16;             // 32 * WPAD                  ~130KB
    float* wxh_sm = w_sm + 32 * WPAD;                // 128 * 32                    16KB
    float* red_sm = wxh_sm + V_ * 32;                // 512 * 8                     16KB
    float* bh_sm  = red_sm + THREADS_A * 8;          // 32
    int*   x_sm   = (int*)(bh_sm + 32);              // 16

    const int tid   = threadIdx.x;
    const int bg    = blockIdx.x >> 5;               // batch group 0..3
    const int cg    = blockIdx.x & 31;               // col group   0..31
    const int cbase = cg * 32;
    const int boff  = bg * 16;

    // One-time preload: W_hh col slice (32 cols), W_xh slice, bias.
    for (int i = tid; i < H_ * 32; i += THREADS_A) {
        int k = i >> 5, c = i & 31;
        w_sm[c * WPAD + k] = W_hh[(size_t)k * H_ + cbase + c];
    }
    for (int i = tid; i < V_ * 32; i += THREADS_A) {
        int v = i >> 5, c = i & 31;
        wxh_sm[i] = W_xh[(size_t)v * H_ + cbase + c];
    }
    if (tid < 32) bh_sm[tid] = b_h[cbase + tid];
    __syncthreads();

    const int g  = tid & 63;        // 64 groups = 4 batch-quads x 16 col-pairs
    const int kg = tid >> 6;        // k-split group 0..7 (64 k each per tile)
    const int b0 = (g & 3) * 4;     // 4 consecutive local batches
    const int c0 = (g >> 2) * 2;    // 2 consecutive local cols

    // Parallel-tail mapping: 512 outputs, exactly 1 per thread.
    const int tcol = tid >> 4;            // 0..31
    const int tb   = tid & 15;            // 0..15
    const int tg   = (tcol >> 1) * 4 + (tb >> 2);
    const int ti   = (tcol & 1) * 4 + (tb & 3);

    const float* wp0 = w_sm + c0 * WPAD;
    const float* wp1 = wp0 + WPAD;
    uint32_t hs_base = (uint32_t)__cvta_generic_to_shared(h_sm);

    for (int t = 0; t < S_; ++t) {
        const float* hsrc = g_hid + (size_t)t * HB + boff;
        if (tid < 16) x_sm[tid] = x[(size_t)(boff + tid) * S_ + t];

        float acc[8];
#pragma unroll
        for (int i = 0; i < 8; ++i) acc[i] = 0.f;

        stage_tile(hs_base, hsrc, tid);
        asm volatile("cp.async.commit_group;\n" ::: "memory");

#pragma unroll
        for (int tile = 0; tile < 2; ++tile) {
            if (tile == 0) {
                stage_tile(hs_base + (uint32_t)(512 * 16 * 4),
                           hsrc + (size_t)512 * B_, tid);
                asm volatile("cp.async.commit_group;\n" ::: "memory");
                asm volatile("cp.async.wait_group 1;\n" ::: "memory");
            } else {
                asm volatile("cp.async.wait_group 0;\n" ::: "memory");
            }
            __syncthreads();

            const float* hp = h_sm + tile * (512 * 16) + (kg * 64) * 16 + b0;
            const float* wa = wp0 + tile * 512 + kg * 64;
            const float* wb = wp1 + tile * 512 + kg * 64;
#pragma unroll
            for (int j = 0; j < 64; j += 4) {
                float4 wa4 = *(const float4*)(wa + j);
                float4 wb4 = *(const float4*)(wb + j);
#pragma unroll
                for (int jj = 0; jj < 4; ++jj) {
                    float4 hv = *(const float4*)(hp + (j + jj) * 16);
                    float wax = (&wa4.x)[jj];
                    float wbx = (&wb4.x)[jj];
                    acc[0] += hv.x * wax; acc[1] += hv.y * wax;
                    acc[2] += hv.z * wax; acc[3] += hv.w * wax;
                    acc[4] += hv.x * wbx; acc[5] += hv.y * wbx;
                    acc[6] += hv.z * wbx; acc[7] += hv.w * wbx;
                }
            }
            // no mid-loop sync needed: tile 1 uses the other buffer (R8-proven)
        }

        // k-split partials -> smem: thread (kg, g) at red[(kg*64+g)*8 + i]
        *(float4*)(red_sm + tid * 8)     = make_float4(acc[0], acc[1], acc[2], acc[3]);
        *(float4*)(red_sm + tid * 8 + 4) = make_float4(acc[4], acc[5], acc[6], acc[7]);
        __syncthreads();

        // Parallel tail: each thread reduces 8 partials for 1 output
        // (col tcol, batch tb), tanh, store h[t+1].
        {
            float s0 = 0.f;
#pragma unroll
            for (int kk = 0; kk < 8; ++kk)
                s0 += red_sm[(kk * 64 + tg) * 8 + ti];
            float v0 = tanhf(s0 + wxh_sm[x_sm[tb] * 32 + tcol] + bh_sm[tcol]);
            g_hid[(size_t)(t + 1) * HB + (size_t)(cbase + tcol) * B_ + boff + tb] = v0;
            if (t == S_ - 1)
                hfinal_out[(size_t)(boff + tb) * H_ + cbase + tcol] = v0;
        }

        // R1-proven full barrier, among this batch-group's 32 CTAs only.
        __threadfence();
        __syncthreads();
        if (tid == 0) {
            unsigned target = (unsigned)(t + 1) * 32u;
            atomicAdd(&g_cntb[bg * 32], 1u);
            volatile unsigned* vc = &g_cntb[bg * 32];
            while ((int)(*vc - target) < 0) { }
            __threadfence();
        }
        __syncthreads();
    }
}

// ---------------------------------------------------------------------------
// logits = hidden @ W_out + b_out.  M=32768 (m = t*64+b), N=128, K=1024.
// A read from g_hid (t+1, k, b). 256 CTAs, 128x128 tile, 8x8 micro. (proven)
// ---------------------------------------------------------------------------
__global__ __launch_bounds__(256) void rnn_logits(
    const float* __restrict__ W_out, const float* __restrict__ b_out,
    float* __restrict__ out)
{
    __shared__ float a_sm[32][128];
    __shared__ float b_sm[32][128];
    const int tid = threadIdx.x;
    const int M0  = blockIdx.x * 128;
    const int t0  = M0 >> 6;
    const int tx  = tid & 15, ty = tid >> 4;

    float acc[8][8];
#pragma unroll
    for (int i = 0; i < 8; ++i)
#pragma unroll
        for (int j = 0; j < 8; ++j) acc[i][j] = 0.f;

    for (int kt = 0; kt < 32; ++kt) {
        int k0 = kt * 32;
#pragma unroll
        for (int j2 = 0; j2 < 4; ++j2) {
            int q = tid + j2 * 256;
            int k = q >> 5;
            int m = (q & 31) << 2;
            const float* asrc = g_hid + (size_t)(t0 + (m >> 6) + 1) * HB +
                                (size_t)(k0 + k) * B_ + (m & 63);
            *(float4*)&a_sm[k][m] = *(const float4*)asrc;
            *(float4*)&b_sm[k][m] = *(const float4*)&W_out[(size_t)(k0 + k) * V_ + m];
        }
        __syncthreads();
#pragma unroll
        for (int k = 0; k < 32; ++k) {
            float4 a0 = *(float4*)&a_sm[k][ty * 8];
            float4 a1 = *(float4*)&a_sm[k][ty * 8 + 4];
            float4 w0 = *(float4*)&b_sm[k][tx * 8];
            float4 w1 = *(float4*)&b_sm[k][tx * 8 + 4];
            float av[8] = {a0.x, a0.y, a0.z, a0.w, a1.x, a1.y, a1.z, a1.w};
            float bv[8] = {w0.x, w0.y, w0.z, w0.w, w1.x, w1.y, w1.z, w1.w};
#pragma unroll
            for (int i = 0; i < 8; ++i)
#pragma unroll
                for (int j = 0; j < 8; ++j) acc[i][j] += av[i] * bv[j];
        }
        __syncthreads();
    }

    float bo[8];
#pragma unroll
    for (int j = 0; j < 8; ++j) bo[j] = b_out[tx * 8 + j];
#pragma unroll
    for (int i = 0; i < 8; ++i) {
        int mg = M0 + ty * 8 + i;
        int tt = mg >> 6, b = mg & 63;
        float* op = out + ((size_t)b * S_ + tt) * V_ + tx * 8;
        *(float4*)op       = make_float4(acc[i][0] + bo[0], acc[i][1] + bo[1],
                                         acc[i][2] + bo[2], acc[i][3] + bo[3]);
        *(float4*)(op + 4) = make_float4(acc[i][4] + bo[4], acc[i][5] + bo[5],
                                         acc[i][6] + bo[6], acc[i][7] + bo[7]);
    }
}

// ---------------------------------------------------------------------------
extern "C" void kernel_launch(void* const* d_in, const int* in_sizes, int n_in,
                              void* d_out, int out_size) {
    (void)in_sizes; (void)n_in; (void)out_size;
    const int*   x     = (const int*)  d_in[0];
    const float* h0    = (const float*)d_in[1];
    const float* W_xh  = (const float*)d_in[2];
    const float* W_hh  = (const float*)d_in[3];
    const float* b_h   = (const float*)d_in[4];
    const float* W_out = (const float*)d_in[5];
    const float* b_out = (const float*)d_in[6];
    float* out = (float*)d_out;

    const int SMEM_A = (2 * 512 * 16 + 32 * WPAD + V_ * 32 + THREADS_A * 8 + 32)
                           * (int)sizeof(float) + 16 * (int)sizeof(int);
    cudaFuncSetAttribute(rnn_recur, cudaFuncAttributeMaxDynamicSharedMemorySize, SMEM_A);

    // Idempotent init launched 5x so rnn_recur sits at kernel index 5 —
    // ncu's "-s 5 -c 1" then profiles the persistent kernel instead of init.
    rnn_init<<<(HB + 255) / 256, 256>>>(h0);
    rnn_init<<<(HB + 255) / 256, 256>>>(h0);
    rnn_init<<<(HB + 255) / 256, 256>>>(h0);
    rnn_init<<<(HB + 255) / 256, 256>>>(h0);
    rnn_init<<<(HB + 255) / 256, 256>>>(h0);
    rnn_recur<<<128, THREADS_A, SMEM_A>>>(x, W_xh, W_hh, b_h,
                                          out + (size_t)B_ * S_ * V_);
    rnn_logits<<<(B_ * S_) / 128, 256>>>(W_out, b_out, out);
}

// round 11
// speedup vs baseline: 1.3138x; 1.0327x over previous
#include <cuda_runtime.h>
#include <cstdint>

#define B_ 64
#define S_ 512
#define H_ 1024
#define V_ 128
#define THREADS_A 256
#define HB (H_ * B_)   /* 65536 floats per time slot, layout [h][b] */
#define WPAD 1036      /* w_sm column stride (floats), 16B-aligned */

// Hidden-state history, layout (slot, h, b); slot 0 = initial h (transposed),
// slot t+1 = hidden after step t.
__device__ __align__(16) float g_hid[(size_t)(S_ + 1) * HB];
// One full-barrier counter per batch-group (4 pools of 32 CTAs), 128B apart.
__device__ unsigned int g_cntb[4 * 32];
__device__ float g_dummy;

// ---------------------------------------------------------------------------
__global__ void rnn_init(const float* __restrict__ h0) {
    int i = blockIdx.x * blockDim.x + threadIdx.x;
    if (i < 4 * 32) g_cntb[i] = 0u;
    if (i < HB) {
        int b = i >> 10;        // i = b*1024 + h
        int hh = i & 1023;
        g_hid[(size_t)hh * B_ + b] = h0[i];
    }
}

// Tiny distinct kernels to identify ncu's skip offset (and shift rnn_recur
// into the profiled slot under the offset-2 hypothesis).
__global__ void rnn_dmy1(const float* __restrict__ h0) {
    if (threadIdx.x == 0 && blockIdx.x == 0) g_dummy = h0[0];
}
__global__ void rnn_dmy2(const float* __restrict__ h0) {
    if (threadIdx.x == 0 && blockIdx.x == 0) g_dummy = h0[1];
}

// ---------------------------------------------------------------------------
// cp.async staging of one k-sub-tile of h: 256 k-rows x 16 batches = 16 KB.
// ---------------------------------------------------------------------------
__device__ __forceinline__ void stage_sub(uint32_t dst_s, const float* src_base, int tid) {
#pragma unroll
    for (int j = 0; j < 4; ++j) {
        int c = tid + j * THREADS_A;               // 0..1023 16B chunks
        int row = c >> 2, q = c & 3;
        asm volatile("cp.async.cg.shared.global [%0], [%1], 16;\n"
                     :: "r"(dst_s + (uint32_t)c * 16u),
                        "l"(src_base + (size_t)row * B_ + q * 4)
                     : "memory");
    }
}

// ---------------------------------------------------------------------------
// Persistent recurrence. 128 CTAs x 256 threads. CTA (bg, cg) owns
// batches [16bg,16bg+16) x cols [32cg,32cg+32). Four decoupled pools of 32
// CTAs (per bg) with the R1-proven full-barrier idiom. h staged as 4
// independent 16KB sub-tiles (4 cp.async groups) so compute starts after a
// 16KB fetch instead of 32KB; no buffer reuse within a step.
// ---------------------------------------------------------------------------
__global__ __launch_bounds__(THREADS_A, 1) void rnn_recur(
    const int* __restrict__ x, const float* __restrict__ W_xh,
    const float* __restrict__ W_hh, const float* __restrict__ b_h,
    float* __restrict__ hfinal_out)
{
    extern __shared__ float sm[];
    float* h_sm   = sm;                              // 4 * 256 * 16 floats   64KB
    float* w_sm   = h_sm + 4 * 256 * 16;             // 32 * WPAD           ~130KB
    float* wxh_sm = w_sm + 32 * WPAD;                // 128 * 32              16KB
    float* red_sm = wxh_sm + V_ * 32;                // 256 * 8                8KB
    float* bh_sm  = red_sm + THREADS_A * 8;          // 32
    int*   x_sm   = (int*)(bh_sm + 32);              // 16

    const int tid   = threadIdx.x;
    const int bg    = blockIdx.x >> 5;               // batch group 0..3
    const int cg    = blockIdx.x & 31;               // col group   0..31
    const int cbase = cg * 32;
    const int boff  = bg * 16;

    // One-time preload: W_hh col slice (32 cols), W_xh slice, bias.
    for (int i = tid; i < H_ * 32; i += THREADS_A) {
        int k = i >> 5, c = i & 31;
        w_sm[c * WPAD + k] = W_hh[(size_t)k * H_ + cbase + c];
    }
    for (int i = tid; i < V_ * 32; i += THREADS_A) {
        int v = i >> 5, c = i & 31;
        wxh_sm[i] = W_xh[(size_t)v * H_ + cbase + c];
    }
    if (tid < 32) bh_sm[tid] = b_h[cbase + tid];
    __syncthreads();

    const int g  = tid & 63;        // 64 groups = 4 batch-quads x 16 col-pairs
    const int kg = tid >> 6;        // k-split group 0..3 (64 k per sub-tile)
    const int b0 = (g & 3) * 4;     // 4 consecutive local batches
    const int c0 = (g >> 2) * 2;    // 2 consecutive local cols

    // Parallel-tail mapping (proven): 2 outputs per thread.
    const int tcol = tid >> 3;            // 0..31
    const int tb   = (tid & 7) * 2;       // 0,2,..,14
    const int tg   = (tcol >> 1) * 4 + (tb >> 2);
    const int ti   = (tcol & 1) * 4 + (tb & 3);

    const float* wp0 = w_sm + c0 * WPAD;
    const float* wp1 = wp0 + WPAD;
    uint32_t hs_base = (uint32_t)__cvta_generic_to_shared(h_sm);

    for (int t = 0; t < S_; ++t) {
        const float* hsrc = g_hid + (size_t)t * HB + boff;
        if (tid < 16) x_sm[tid] = x[(size_t)(boff + tid) * S_ + t];

        float acc[8];
#pragma unroll
        for (int i = 0; i < 8; ++i) acc[i] = 0.f;

        // Stage all 4 sub-tiles up-front, one commit group each.
#pragma unroll
        for (int s = 0; s < 4; ++s) {
            stage_sub(hs_base + (uint32_t)(s * 256 * 16 * 4),
                      hsrc + (size_t)(s * 256) * B_, tid);
            asm volatile("cp.async.commit_group;\n" ::: "memory");
        }

#pragma unroll
        for (int s = 0; s < 4; ++s) {
            if (s == 0)      asm volatile("cp.async.wait_group 3;\n" ::: "memory");
            else if (s == 1) asm volatile("cp.async.wait_group 2;\n" ::: "memory");
            else if (s == 2) asm volatile("cp.async.wait_group 1;\n" ::: "memory");
            else             asm volatile("cp.async.wait_group 0;\n" ::: "memory");
            __syncthreads();

            const float* hp = h_sm + s * (256 * 16) + (kg * 64) * 16 + b0;
            const float* wa = wp0 + s * 256 + kg * 64;
            const float* wb = wp1 + s * 256 + kg * 64;
#pragma unroll
            for (int j = 0; j < 64; j += 4) {
                float4 wa4 = *(const float4*)(wa + j);
                float4 wb4 = *(const float4*)(wb + j);
#pragma unroll
                for (int jj = 0; jj < 4; ++jj) {
                    float4 hv = *(const float4*)(hp + (j + jj) * 16);
                    float wax = (&wa4.x)[jj];
                    float wbx = (&wb4.x)[jj];
                    acc[0] += hv.x * wax; acc[1] += hv.y * wax;
                    acc[2] += hv.z * wax; acc[3] += hv.w * wax;
                    acc[4] += hv.x * wbx; acc[5] += hv.y * wbx;
                    acc[6] += hv.z * wbx; acc[7] += hv.w * wbx;
                }
            }
            // No per-sub-tile trailing sync: each buffer is written once per
            // step and its wait_group+sync precedes its reads.
        }

        // k-split partials -> smem
        *(float4*)(red_sm + tid * 8)     = make_float4(acc[0], acc[1], acc[2], acc[3]);
        *(float4*)(red_sm + tid * 8 + 4) = make_float4(acc[4], acc[5], acc[6], acc[7]);
        __syncthreads();

        // Parallel tail: reduce 4 partials for 2 outputs, tanh, store h[t+1].
        {
            float s0 = 0.f, s1 = 0.f;
#pragma unroll
            for (int kk = 0; kk < 4; ++kk) {
                float2 v = *(const float2*)&red_sm[(kk * 64 + tg) * 8 + ti];
                s0 += v.x; s1 += v.y;
            }
            float wb0 = wxh_sm[x_sm[tb] * 32 + tcol];
            float wb1 = wxh_sm[x_sm[tb + 1] * 32 + tcol];
            float v0 = tanhf(s0 + wb0 + bh_sm[tcol]);
            float v1 = tanhf(s1 + wb1 + bh_sm[tcol]);
            *(float2*)&g_hid[(size_t)(t + 1) * HB +
                             (size_t)(cbase + tcol) * B_ + boff + tb] =
                make_float2(v0, v1);
            if (t == S_ - 1) {
                hfinal_out[(size_t)(boff + tb) * H_ + cbase + tcol]     = v0;
                hfinal_out[(size_t)(boff + tb + 1) * H_ + cbase + tcol] = v1;
            }
        }

        // R1-proven full barrier, among this batch-group's 32 CTAs only.
        __threadfence();
        __syncthreads();
        if (tid == 0) {
            unsigned target = (unsigned)(t + 1) * 32u;
            atomicAdd(&g_cntb[bg * 32], 1u);
            volatile unsigned* vc = &g_cntb[bg * 32];
            while ((int)(*vc - target) < 0) { }
            __threadfence();
        }
        __syncthreads();
    }
}

// ---------------------------------------------------------------------------
// logits = hidden @ W_out + b_out.  M=32768 (m = t*64+b), N=128, K=1024.
// A read from g_hid (t+1, k, b). 256 CTAs, 128x128 tile, 8x8 micro. (proven)
// ---------------------------------------------------------------------------
__global__ __launch_bounds__(256) void rnn_logits(
    const float* __restrict__ W_out, const float* __restrict__ b_out,
    float* __restrict__ out)
{
    __shared__ float a_sm[32][128];
    __shared__ float b_sm[32][128];
    const int tid = threadIdx.x;
    const int M0  = blockIdx.x * 128;
    const int t0  = M0 >> 6;
    const int tx  = tid & 15, ty = tid >> 4;

    float acc[8][8];
#pragma unroll
    for (int i = 0; i < 8; ++i)
#pragma unroll
        for (int j = 0; j < 8; ++j) acc[i][j] = 0.f;

    for (int kt = 0; kt < 32; ++kt) {
        int k0 = kt * 32;
#pragma unroll
        for (int j2 = 0; j2 < 4; ++j2) {
            int q = tid + j2 * 256;
            int k = q >> 5;
            int m = (q & 31) << 2;
            const float* asrc = g_hid + (size_t)(t0 + (m >> 6) + 1) * HB +
                                (size_t)(k0 + k) * B_ + (m & 63);
            *(float4*)&a_sm[k][m] = *(const float4*)asrc;
            *(float4*)&b_sm[k][m] = *(const float4*)&W_out[(size_t)(k0 + k) * V_ + m];
        }
        __syncthreads();
#pragma unroll
        for (int k = 0; k < 32; ++k) {
            float4 a0 = *(float4*)&a_sm[k][ty * 8];
            float4 a1 = *(float4*)&a_sm[k][ty * 8 + 4];
            float4 w0 = *(float4*)&b_sm[k][tx * 8];
            float4 w1 = *(float4*)&b_sm[k][tx * 8 + 4];
            float av[8] = {a0.x, a0.y, a0.z, a0.w, a1.x, a1.y, a1.z, a1.w};
            float bv[8] = {w0.x, w0.y, w0.z, w0.w, w1.x, w1.y, w1.z, w1.w};
#pragma unroll
            for (int i = 0; i < 8; ++i)
#pragma unroll
                for (int j = 0; j < 8; ++j) acc[i][j] += av[i] * bv[j];
        }
        __syncthreads();
    }

    float bo[8];
#pragma unroll
    for (int j = 0; j < 8; ++j) bo[j] = b_out[tx * 8 + j];
#pragma unroll
    for (int i = 0; i < 8; ++i) {
        int mg = M0 + ty * 8 + i;
        int tt = mg >> 6, b = mg & 63;
        float* op = out + ((size_t)b * S_ + tt) * V_ + tx * 8;
        *(float4*)op       = make_float4(acc[i][0] + bo[0], acc[i][1] + bo[1],
                                         acc[i][2] + bo[2], acc[i][3] + bo[3]);
        *(float4*)(op + 4) = make_float4(acc[i][4] + bo[4], acc[i][5] + bo[5],
                                         acc[i][6] + bo[6], acc[i][7] + bo[7]);
    }
}

// ---------------------------------------------------------------------------
extern "C" void kernel_launch(void* const* d_in, const int* in_sizes, int n_in,
                              void* d_out, int out_size) {
    (void)in_sizes; (void)n_in; (void)out_size;
    const int*   x     = (const int*)  d_in[0];
    const float* h0    = (const float*)d_in[1];
    const float* W_xh  = (const float*)d_in[2];
    const float* W_hh  = (const float*)d_in[3];
    const float* b_h   = (const float*)d_in[4];
    const float* W_out = (const float*)d_in[5];
    const float* b_out = (const float*)d_in[6];
    float* out = (float*)d_out;

    const int SMEM_A = (4 * 256 * 16 + 32 * WPAD + V_ * 32 + THREADS_A * 8 + 32)
                           * (int)sizeof(float) + 16 * (int)sizeof(int);
    cudaFuncSetAttribute(rnn_recur, cudaFuncAttributeMaxDynamicSharedMemorySize, SMEM_A);

    // Slot map for ncu offset identification: 0=init, 1=dmy1, 2=dmy2,
    // 3=recur (profiled under the offset-2 hypothesis), 4=logits.
    rnn_init<<<(HB + 255) / 256, 256>>>(h0);
    rnn_dmy1<<<1, 32>>>(h0);
    rnn_dmy2<<<1, 32>>>(h0);
    rnn_recur<<<128, THREADS_A, SMEM_A>>>(x, W_xh, W_hh, b_h,
                                          out + (size_t)B_ * S_ * V_);
    rnn_logits<<<(B_ * S_) / 128, 256>>>(W_out, b_out, out);
}

// round 12
// speedup vs baseline: 1.5445x; 1.1756x over previous
#include <cuda_runtime.h>
#include <cstdint>

#define B_ 64
#define S_ 512
#define H_ 1024
#define V_ 128
#define THREADS_A 256
#define HB (H_ * B_)   /* 65536 floats per time slot, layout [h][b] */
#define RPAD 516       /* red plane stride (floats), 16B-aligned, bank-skewed */

// Hidden-state history, layout (slot, h, b); slot 0 = initial h (transposed),
// slot t+1 = hidden after step t.
__device__ __align__(16) float g_hid[(size_t)(S_ + 1) * HB];
// One full-barrier counter per batch-group (4 pools of 32 CTAs), 128B apart.
__device__ unsigned int g_cntb[4 * 32];
__device__ float g_dummy;

// ---------------------------------------------------------------------------
__global__ void rnn_init(const float* __restrict__ h0) {
    int i = blockIdx.x * blockDim.x + threadIdx.x;
    if (i < 4 * 32) g_cntb[i] = 0u;
    if (i < HB) {
        int b = i >> 10;        // i = b*1024 + h
        int hh = i & 1023;
        g_hid[(size_t)hh * B_ + b] = h0[i];
    }
}
// Distinct tiny kernels keep rnn_recur in ncu's profiled slot (offset-2).
__global__ void rnn_dmy1(const float* __restrict__ h0) {
    if (threadIdx.x == 0 && blockIdx.x == 0) g_dummy = h0[0];
}
__global__ void rnn_dmy2(const float* __restrict__ h0) {
    if (threadIdx.x == 0 && blockIdx.x == 0) g_dummy = h0[1];
}

// ---------------------------------------------------------------------------
// cp.async staging of one k-sub-tile of h: 256 k-rows x 16 batches = 16 KB.
// ---------------------------------------------------------------------------
__device__ __forceinline__ void stage_sub(uint32_t dst_s, const float* src_base, int tid) {
#pragma unroll
    for (int j = 0; j < 4; ++j) {
        int c = tid + j * THREADS_A;               // 0..1023 16B chunks
        int row = c >> 2, q = c & 3;
        asm volatile("cp.async.cg.shared.global [%0], [%1], 16;\n"
                     :: "r"(dst_s + (uint32_t)c * 16u),
                        "l"(src_base + (size_t)row * B_ + q * 4)
                     : "memory");
    }
}

// ---------------------------------------------------------------------------
// Persistent recurrence. 128 CTAs x 256 threads. CTA (bg, cg) owns
// batches [16bg,16bg+16) x cols [32cg,32cg+32). Four decoupled pools of 32
// CTAs (per bg), R1-proven full-barrier idiom.
// NEW: thread tile 8 batches x 4 cols (32 acc), k-split 16 — SMEM bytes per
// FMA drop 3.0 -> 1.5 (profile showed l1tex 57.6% was the binder).
// W_hh stored k-major [k][32]; 16-deep reduction aliased into h_sm.
// ---------------------------------------------------------------------------
__global__ __launch_bounds__(THREADS_A, 1) void rnn_recur(
    const int* __restrict__ x, const float* __restrict__ W_xh,
    const float* __restrict__ W_hh, const float* __restrict__ b_h,
    float* __restrict__ hfinal_out)
{
    extern __shared__ float sm[];
    float* h_sm   = sm;                              // 4 * 256 * 16 floats  64KB
    float* red_sm = sm;                              // ALIAS: 16*RPAD = 33KB
    float* w_sm   = h_sm + 4 * 256 * 16;             // 1024 * 32           128KB
    float* wxh_sm = w_sm + H_ * 32;                  // 128 * 32             16KB
    float* bh_sm  = wxh_sm + V_ * 32;                // 32
    int*   x_sm   = (int*)(bh_sm + 32);              // 16

    const int tid   = threadIdx.x;
    const int bg    = blockIdx.x >> 5;               // batch group 0..3
    const int cg    = blockIdx.x & 31;               // col group   0..31
    const int cbase = cg * 32;
    const int boff  = bg * 16;

    // One-time preload: W_hh slice k-major [k][32], W_xh slice, bias.
    for (int i = tid; i < H_ * 32; i += THREADS_A) {
        int k = i >> 5, c = i & 31;
        w_sm[i] = W_hh[(size_t)k * H_ + cbase + c];
    }
    for (int i = tid; i < V_ * 32; i += THREADS_A) {
        int v = i >> 5, c = i & 31;
        wxh_sm[i] = W_xh[(size_t)v * H_ + cbase + c];
    }
    if (tid < 32) bh_sm[tid] = b_h[cbase + tid];
    __syncthreads();

    const int kg = tid >> 4;        // k-split group 0..15 (64 k each)
    const int gb = (tid >> 3) & 1;  // batch half: 8 batches
    const int gc = tid & 7;         // col quad: 4 cols
    const int b0 = gb * 8;
    const int c0 = gc * 4;

    // Parallel-tail mapping (proven shape): 2 outputs per thread.
    const int tcol = tid >> 3;            // 0..31
    const int tb   = (tid & 7) * 2;       // 0,2,..,14

    uint32_t hs_base = (uint32_t)__cvta_generic_to_shared(h_sm);

    for (int t = 0; t < S_; ++t) {
        const float* hsrc = g_hid + (size_t)t * HB + boff;
        if (tid < 16) x_sm[tid] = x[(size_t)(boff + tid) * S_ + t];

        float acc[4][8];
#pragma unroll
        for (int i = 0; i < 4; ++i)
#pragma unroll
            for (int j = 0; j < 8; ++j) acc[i][j] = 0.f;

        // Stage all 4 sub-tiles up-front, one commit group each.
#pragma unroll
        for (int s = 0; s < 4; ++s) {
            stage_sub(hs_base + (uint32_t)(s * 256 * 16 * 4),
                      hsrc + (size_t)(s * 256) * B_, tid);
            asm volatile("cp.async.commit_group;\n" ::: "memory");
        }

#pragma unroll
        for (int s = 0; s < 4; ++s) {
            if (s == 0)      asm volatile("cp.async.wait_group 3;\n" ::: "memory");
            else if (s == 1) asm volatile("cp.async.wait_group 2;\n" ::: "memory");
            else if (s == 2) asm volatile("cp.async.wait_group 1;\n" ::: "memory");
            else             asm volatile("cp.async.wait_group 0;\n" ::: "memory");
            __syncthreads();

            // This thread's 16 k of sub-tile s: local k = kg*16 + j.
            const float* hq = h_sm + s * 4096 + (kg * 16) * 16 + b0;
            const float* wq = w_sm + (s * 256 + kg * 16) * 32 + c0;
#pragma unroll
            for (int j = 0; j < 16; ++j) {
                float4 wv = *(const float4*)(wq);
                float4 hA = *(const float4*)(hq);
                float4 hB = *(const float4*)(hq + 4);
#pragma unroll
                for (int cc = 0; cc < 4; ++cc) {
                    float w = (&wv.x)[cc];
                    acc[cc][0] += hA.x * w; acc[cc][1] += hA.y * w;
                    acc[cc][2] += hA.z * w; acc[cc][3] += hA.w * w;
                    acc[cc][4] += hB.x * w; acc[cc][5] += hB.y * w;
                    acc[cc][6] += hB.z * w; acc[cc][7] += hB.w * w;
                }
                hq += 16;
                wq += 32;
            }
        }

        // red_sm aliases h_sm: wait for all h reads to finish first.
        __syncthreads();
        {
            float* rp = red_sm + kg * RPAD + c0 * 16 + b0;
#pragma unroll
            for (int cc = 0; cc < 4; ++cc) {
                *(float4*)(rp + cc * 16)     = make_float4(acc[cc][0], acc[cc][1],
                                                           acc[cc][2], acc[cc][3]);
                *(float4*)(rp + cc * 16 + 4) = make_float4(acc[cc][4], acc[cc][5],
                                                           acc[cc][6], acc[cc][7]);
            }
        }
        __syncthreads();

        // Parallel tail: reduce 16 partials for 2 outputs, tanh, store h[t+1].
        {
            float s0 = 0.f, s1 = 0.f;
#pragma unroll
            for (int kq = 0; kq < 16; ++kq) {
                float2 v = *(const float2*)&red_sm[kq * RPAD + tcol * 16 + tb];
                s0 += v.x; s1 += v.y;
            }
            float wb0 = wxh_sm[x_sm[tb] * 32 + tcol];
            float wb1 = wxh_sm[x_sm[tb + 1] * 32 + tcol];
            float v0 = tanhf(s0 + wb0 + bh_sm[tcol]);
            float v1 = tanhf(s1 + wb1 + bh_sm[tcol]);
            *(float2*)&g_hid[(size_t)(t + 1) * HB +
                             (size_t)(cbase + tcol) * B_ + boff + tb] =
                make_float2(v0, v1);
            if (t == S_ - 1) {
                hfinal_out[(size_t)(boff + tb) * H_ + cbase + tcol]     = v0;
                hfinal_out[(size_t)(boff + tb + 1) * H_ + cbase + tcol] = v1;
            }
        }

        // R1-proven full barrier, among this batch-group's 32 CTAs only.
        __threadfence();
        __syncthreads();
        if (tid == 0) {
            unsigned target = (unsigned)(t + 1) * 32u;
            atomicAdd(&g_cntb[bg * 32], 1u);
            volatile unsigned* vc = &g_cntb[bg * 32];
            while ((int)(*vc - target) < 0) { }
            __threadfence();
        }
        __syncthreads();
    }
}

// ---------------------------------------------------------------------------
// logits = hidden @ W_out + b_out.  M=32768 (m = t*64+b), N=128, K=1024.
// A read from g_hid (t+1, k, b). 256 CTAs, 128x128 tile, 8x8 micro. (proven)
// ---------------------------------------------------------------------------
__global__ __launch_bounds__(256) void rnn_logits(
    const float* __restrict__ W_out, const float* __restrict__ b_out,
    float* __restrict__ out)
{
    __shared__ float a_sm[32][128];
    __shared__ float b_sm[32][128];
    const int tid = threadIdx.x;
    const int M0  = blockIdx.x * 128;
    const int t0  = M0 >> 6;
    const int tx  = tid & 15, ty = tid >> 4;

    float acc[8][8];
#pragma unroll
    for (int i = 0; i < 8; ++i)
#pragma unroll
        for (int j = 0; j < 8; ++j) acc[i][j] = 0.f;

    for (int kt = 0; kt < 32; ++kt) {
        int k0 = kt * 32;
#pragma unroll
        for (int j2 = 0; j2 < 4; ++j2) {
            int q = tid + j2 * 256;
            int k = q >> 5;
            int m = (q & 31) << 2;
            const float* asrc = g_hid + (size_t)(t0 + (m >> 6) + 1) * HB +
                                (size_t)(k0 + k) * B_ + (m & 63);
            *(float4*)&a_sm[k][m] = *(const float4*)asrc;
            *(float4*)&b_sm[k][m] = *(const float4*)&W_out[(size_t)(k0 + k) * V_ + m];
        }
        __syncthreads();
#pragma unroll
        for (int k = 0; k < 32; ++k) {
            float4 a0 = *(float4*)&a_sm[k][ty * 8];
            float4 a1 = *(float4*)&a_sm[k][ty * 8 + 4];
            float4 w0 = *(float4*)&b_sm[k][tx * 8];
            float4 w1 = *(float4*)&b_sm[k][tx * 8 + 4];
            float av[8] = {a0.x, a0.y, a0.z, a0.w, a1.x, a1.y, a1.z, a1.w};
            float bv[8] = {w0.x, w0.y, w0.z, w0.w, w1.x, w1.y, w1.z, w1.w};
#pragma unroll
            for (int i = 0; i < 8; ++i)
#pragma unroll
                for (int j = 0; j < 8; ++j) acc[i][j] += av[i] * bv[j];
        }
        __syncthreads();
    }

    float bo[8];
#pragma unroll
    for (int j = 0; j < 8; ++j) bo[j] = b_out[tx * 8 + j];
#pragma unroll
    for (int i = 0; i < 8; ++i) {
        int mg = M0 + ty * 8 + i;
        int tt = mg >> 6, b = mg & 63;
        float* op = out + ((size_t)b * S_ + tt) * V_ + tx * 8;
        *(float4*)op       = make_float4(acc[i][0] + bo[0], acc[i][1] + bo[1],
                                         acc[i][2] + bo[2], acc[i][3] + bo[3]);
        *(float4*)(op + 4) = make_float4(acc[i][4] + bo[4], acc[i][5] + bo[5],
                                         acc[i][6] + bo[6], acc[i][7] + bo[7]);
    }
}

// ---------------------------------------------------------------------------
extern "C" void kernel_launch(void* const* d_in, const int* in_sizes, int n_in,
                              void* d_out, int out_size) {
    (void)in_sizes; (void)n_in; (void)out_size;
    const int*   x     = (const int*)  d_in[0];
    const float* h0    = (const float*)d_in[1];
    const float* W_xh  = (const float*)d_in[2];
    const float* W_hh  = (const float*)d_in[3];
    const float* b_h   = (const float*)d_in[4];
    const float* W_out = (const float*)d_in[5];
    const float* b_out = (const float*)d_in[6];
    float* out = (float*)d_out;

    const int SMEM_A = (4 * 256 * 16 + H_ * 32 + V_ * 32 + 32) * (int)sizeof(float)
                       + 16 * (int)sizeof(int);
    cudaFuncSetAttribute(rnn_recur, cudaFuncAttributeMaxDynamicSharedMemorySize, SMEM_A);

    // Slot map (proven): 0=init, 1=dmy1, 2=dmy2, 3=recur (profiled), 4=logits.
    rnn_init<<<(HB + 255) / 256, 256>>>(h0);
    rnn_dmy1<<<1, 32>>>(h0);
    rnn_dmy2<<<1, 32>>>(h0);
    rnn_recur<<<128, THREADS_A, SMEM_A>>>(x, W_xh, W_hh, b_h,
                                          out + (size_t)B_ * S_ * V_);
    rnn_logits<<<(B_ * S_) / 128, 256>>>(W_out, b_out, out);
}